// round 1
// baseline (speedup 1.0000x reference)
#include <cuda_runtime.h>
#include <cuda_bf16.h>
#include <math.h>

// Problem constants
#define BB   2
#define TT   2048
#define DD   1024
#define LL   4
#define HH   16
#define HD   64
#define VV   32000
#define DFF  4096
#define MM   (BB*TT)        // 4096 rows

// Scratch buffers (device globals — no allocation allowed)
__device__ float g_x[MM*DD];
__device__ float g_h[MM*DD];
__device__ float g_q[MM*DD];
__device__ float g_k[MM*DD];
__device__ float g_v[MM*DD];
__device__ float g_att[MM*DD];
__device__ float g_ffn[MM*DFF];

// ---------------------------------------------------------------------------
// Embedding: x[b,t,:] = tok_emb[ctx[b,t],:] + pos_emb[t,:]
// ---------------------------------------------------------------------------
__global__ __launch_bounds__(256) void embed_kernel(
    const int* __restrict__ ctx, const float* __restrict__ tok,
    const float* __restrict__ pos, float* __restrict__ x)
{
    int idx = blockIdx.x * 256 + threadIdx.x;      // over MM*DD
    int d  = idx & (DD - 1);
    int bt = idx >> 10;
    int t  = bt & (TT - 1);
    int v  = ctx[bt];
    x[idx] = tok[(size_t)v * DD + d] + pos[(size_t)t * DD + d];
}

// ---------------------------------------------------------------------------
// LayerNorm: one block (256 thr) per row of 1024
// ---------------------------------------------------------------------------
__global__ __launch_bounds__(256) void ln_kernel(
    const float* __restrict__ x, const float* __restrict__ s,
    const float* __restrict__ b, float* __restrict__ y)
{
    int row = blockIdx.x;
    const float* xr = x + (size_t)row * DD;
    float*       yr = y + (size_t)row * DD;
    int tid = threadIdx.x;

    float v0 = xr[tid], v1 = xr[tid+256], v2 = xr[tid+512], v3 = xr[tid+768];
    float sum = v0+v1+v2+v3;
    float sq  = v0*v0+v1*v1+v2*v2+v3*v3;

    #pragma unroll
    for (int o = 16; o > 0; o >>= 1) {
        sum += __shfl_xor_sync(0xFFFFFFFFu, sum, o);
        sq  += __shfl_xor_sync(0xFFFFFFFFu, sq,  o);
    }
    __shared__ float ssum[8], ssq[8], red[2];
    if ((tid & 31) == 0) { ssum[tid>>5] = sum; ssq[tid>>5] = sq; }
    __syncthreads();
    if (tid < 32) {
        float a = (tid < 8) ? ssum[tid] : 0.f;
        float c = (tid < 8) ? ssq[tid]  : 0.f;
        #pragma unroll
        for (int o = 4; o > 0; o >>= 1) {
            a += __shfl_xor_sync(0xFFFFFFFFu, a, o);
            c += __shfl_xor_sync(0xFFFFFFFFu, c, o);
        }
        if (tid == 0) { red[0] = a; red[1] = c; }
    }
    __syncthreads();
    float mean = red[0] * (1.f/DD);
    float var  = red[1] * (1.f/DD) - mean*mean;
    float inv  = rsqrtf(var + 1e-5f);
    #pragma unroll
    for (int i = 0; i < 4; i++) {
        int c = tid + i*256;
        yr[c] = (xr[c] - mean) * inv * s[c] + b[c];
    }
}

// ---------------------------------------------------------------------------
// SGEMM: C[M,N] = A[M,K] @ B[K,N]  (+bias[n]) (+res[m,n]) (relu)
// 128x128 block tile, BK=8, 256 threads, 8x8 per-thread micro-tile.
// M,N multiples of 128; K multiple of 8.
// mode: bit0 = add bias, bit1 = add residual, bit2 = relu
// ---------------------------------------------------------------------------
__global__ __launch_bounds__(256) void sgemm_kernel(
    int M, int N, int K,
    const float* __restrict__ A, const float* __restrict__ B,
    const float* __restrict__ bias, const float* __restrict__ res,
    float* __restrict__ C, int mode)
{
    __shared__ float As[8][128];
    __shared__ float Bs[8][128];

    int tid = threadIdx.x;
    int bx = blockIdx.x;   // N tile
    int by = blockIdx.y;   // M tile

    const float* Ablk = A + (size_t)by * 128 * K;
    const float* Bblk = B + (size_t)bx * 128;

    int aRow = tid >> 1;          // 0..127
    int aCol = (tid & 1) * 4;     // 0,4
    int bRow = tid >> 5;          // 0..7
    int bCol = (tid & 31) * 4;    // 0..124

    int tr = (tid >> 4) * 8;      // 0..120
    int tc = (tid & 15) * 8;      // 0..120

    float acc[8][8];
    #pragma unroll
    for (int i = 0; i < 8; i++)
        #pragma unroll
        for (int j = 0; j < 8; j++) acc[i][j] = 0.f;

    for (int k0 = 0; k0 < K; k0 += 8) {
        float4 a4 = *(const float4*)(Ablk + (size_t)aRow * K + k0 + aCol);
        float4 b4 = *(const float4*)(Bblk + (size_t)(k0 + bRow) * N + bCol);
        As[aCol+0][aRow] = a4.x;
        As[aCol+1][aRow] = a4.y;
        As[aCol+2][aRow] = a4.z;
        As[aCol+3][aRow] = a4.w;
        *(float4*)&Bs[bRow][bCol] = b4;
        __syncthreads();

        #pragma unroll
        for (int kk = 0; kk < 8; kk++) {
            float4 a0 = *(const float4*)&As[kk][tr];
            float4 a1 = *(const float4*)&As[kk][tr+4];
            float4 c0 = *(const float4*)&Bs[kk][tc];
            float4 c1 = *(const float4*)&Bs[kk][tc+4];
            float ar[8] = {a0.x,a0.y,a0.z,a0.w,a1.x,a1.y,a1.z,a1.w};
            float br[8] = {c0.x,c0.y,c0.z,c0.w,c1.x,c1.y,c1.z,c1.w};
            #pragma unroll
            for (int i = 0; i < 8; i++)
                #pragma unroll
                for (int j = 0; j < 8; j++)
                    acc[i][j] += ar[i] * br[j];
        }
        __syncthreads();
    }

    int grow = by * 128 + tr;
    int gcol = bx * 128 + tc;
    float bsv[8];
    if (mode & 1) {
        float4 q0 = *(const float4*)(bias + gcol);
        float4 q1 = *(const float4*)(bias + gcol + 4);
        bsv[0]=q0.x; bsv[1]=q0.y; bsv[2]=q0.z; bsv[3]=q0.w;
        bsv[4]=q1.x; bsv[5]=q1.y; bsv[6]=q1.z; bsv[7]=q1.w;
    } else {
        #pragma unroll
        for (int j = 0; j < 8; j++) bsv[j] = 0.f;
    }

    #pragma unroll
    for (int i = 0; i < 8; i++) {
        size_t off = (size_t)(grow + i) * N + gcol;
        #pragma unroll
        for (int jj = 0; jj < 2; jj++) {
            float v[4];
            #pragma unroll
            for (int u = 0; u < 4; u++) v[u] = acc[i][jj*4+u] + bsv[jj*4+u];
            if (mode & 2) {
                float4 r4 = *(const float4*)(res + off + jj*4);
                v[0]+=r4.x; v[1]+=r4.y; v[2]+=r4.z; v[3]+=r4.w;
            }
            if (mode & 4) {
                #pragma unroll
                for (int u = 0; u < 4; u++) v[u] = fmaxf(v[u], 0.f);
            }
            float4 o4; o4.x=v[0]; o4.y=v[1]; o4.z=v[2]; o4.w=v[3];
            *(float4*)(C + off + jj*4) = o4;
        }
    }
}

// ---------------------------------------------------------------------------
// Flash attention (causal). Grid (T/128, H, B), 128 threads.
// Thread t owns query row qt*128+t: q,o in registers, online softmax,
// 16-key K/V tiles in shared (broadcast LDS.128 reads).
// Q/K/V/O layout: [B,T,D] with head h at cols [h*64, h*64+64).
// ---------------------------------------------------------------------------
__global__ __launch_bounds__(128) void attn_kernel(
    const float* __restrict__ Q, const float* __restrict__ K,
    const float* __restrict__ V, float* __restrict__ O)
{
    int qt = blockIdx.x, h = blockIdx.y, b = blockIdx.z;
    int tid = threadIdx.x;
    int q_idx = qt * 128 + tid;

    size_t headbase = ((size_t)b * TT) * DD + (size_t)h * HD;
    const float* qp = Q + headbase + (size_t)q_idx * DD;

    float qr[64];
    #pragma unroll
    for (int c = 0; c < 16; c++) {
        float4 t4 = *(const float4*)(qp + c*4);
        qr[4*c+0] = t4.x * 0.125f;
        qr[4*c+1] = t4.y * 0.125f;
        qr[4*c+2] = t4.z * 0.125f;
        qr[4*c+3] = t4.w * 0.125f;
    }
    float ob[64];
    #pragma unroll
    for (int d = 0; d < 64; d++) ob[d] = 0.f;
    float m = -1e30f, lsum = 0.f;

    __shared__ float4 Ks[16][16];
    __shared__ float4 Vs[16][16];

    int kend = qt * 128 + 128;
    for (int k0 = 0; k0 < kend; k0 += 16) {
        __syncthreads();
        #pragma unroll
        for (int i = 0; i < 2; i++) {
            int idx = tid + i*128;
            int r = idx >> 4, c = idx & 15;
            size_t go = headbase + (size_t)(k0 + r) * DD + c*4;
            Ks[r][c] = *(const float4*)(K + go);
            Vs[r][c] = *(const float4*)(V + go);
        }
        __syncthreads();

        float s[16];
        #pragma unroll
        for (int j = 0; j < 16; j++) {
            float acc = 0.f;
            #pragma unroll
            for (int c = 0; c < 16; c++) {
                float4 kk = Ks[j][c];
                acc += qr[4*c+0]*kk.x + qr[4*c+1]*kk.y
                     + qr[4*c+2]*kk.z + qr[4*c+3]*kk.w;
            }
            s[j] = (k0 + j <= q_idx) ? acc : -1e30f;
        }
        float mt = m;
        #pragma unroll
        for (int j = 0; j < 16; j++) mt = fmaxf(mt, s[j]);
        float corr = __expf(m - mt);
        m = mt;
        lsum *= corr;
        #pragma unroll
        for (int d = 0; d < 64; d++) ob[d] *= corr;

        #pragma unroll
        for (int j = 0; j < 16; j++) {
            float p = __expf(s[j] - m);
            lsum += p;
            #pragma unroll
            for (int c = 0; c < 16; c++) {
                float4 vv = Vs[j][c];
                ob[4*c+0] += p * vv.x;
                ob[4*c+1] += p * vv.y;
                ob[4*c+2] += p * vv.z;
                ob[4*c+3] += p * vv.w;
            }
        }
    }

    float inv = 1.f / lsum;
    float* op = O + headbase + (size_t)q_idx * DD;
    #pragma unroll
    for (int c = 0; c < 16; c++) {
        float4 t4;
        t4.x = ob[4*c+0]*inv; t4.y = ob[4*c+1]*inv;
        t4.z = ob[4*c+2]*inv; t4.w = ob[4*c+3]*inv;
        *(float4*)(op + c*4) = t4;
    }
}

// ---------------------------------------------------------------------------
// Host orchestration
// ---------------------------------------------------------------------------
static void run_gemm(const float* A, const float* Bm, const float* bias,
                     const float* res, float* C, int M, int N, int K, int mode)
{
    dim3 grid(N / 128, M / 128);
    sgemm_kernel<<<grid, 256>>>(M, N, K, A, Bm, bias, res, C, mode);
}

extern "C" void kernel_launch(void* const* d_in, const int* in_sizes, int n_in,
                              void* d_out, int out_size)
{
    const int*   ctx  = (const int*)  d_in[0];
    const float* tok  = (const float*)d_in[1];
    const float* pos  = (const float*)d_in[2];
    const float* Wq   = (const float*)d_in[3];
    const float* Wk   = (const float*)d_in[4];
    const float* Wv   = (const float*)d_in[5];
    const float* Wo   = (const float*)d_in[6];
    const float* bo   = (const float*)d_in[7];
    const float* ln1s = (const float*)d_in[8];
    const float* ln1b = (const float*)d_in[9];
    const float* W1   = (const float*)d_in[10];
    const float* b1   = (const float*)d_in[11];
    const float* W2   = (const float*)d_in[12];
    const float* b2   = (const float*)d_in[13];
    const float* ln2s = (const float*)d_in[14];
    const float* ln2b = (const float*)d_in[15];
    const float* lnfs = (const float*)d_in[16];
    const float* lnfb = (const float*)d_in[17];
    const float* Wout = (const float*)d_in[18];
    const float* bout = (const float*)d_in[19];
    float* out = (float*)d_out;

    float *x, *h, *q, *k, *v, *att, *ffn;
    cudaGetSymbolAddress((void**)&x,   g_x);
    cudaGetSymbolAddress((void**)&h,   g_h);
    cudaGetSymbolAddress((void**)&q,   g_q);
    cudaGetSymbolAddress((void**)&k,   g_k);
    cudaGetSymbolAddress((void**)&v,   g_v);
    cudaGetSymbolAddress((void**)&att, g_att);
    cudaGetSymbolAddress((void**)&ffn, g_ffn);

    // Embedding
    embed_kernel<<<(MM*DD)/256, 256>>>(ctx, tok, pos, x);

    for (int l = 0; l < LL; l++) {
        const float* wq = Wq + (size_t)l*DD*DD;
        const float* wk = Wk + (size_t)l*DD*DD;
        const float* wv = Wv + (size_t)l*DD*DD;
        const float* wo = Wo + (size_t)l*DD*DD;
        const float* w1 = W1 + (size_t)l*DD*DFF;
        const float* w2 = W2 + (size_t)l*DFF*DD;

        // h = LN1(x)
        ln_kernel<<<MM, 256>>>(x, ln1s + l*DD, ln1b + l*DD, h);
        // q,k,v = h @ W{q,k,v}
        run_gemm(h, wq, nullptr, nullptr, q, MM, DD, DD, 0);
        run_gemm(h, wk, nullptr, nullptr, k, MM, DD, DD, 0);
        run_gemm(h, wv, nullptr, nullptr, v, MM, DD, DD, 0);
        // attention
        {
            dim3 grid(TT/128, HH, BB);
            attn_kernel<<<grid, 128>>>(q, k, v, att);
        }
        // x = x + att @ Wo + bo
        run_gemm(att, wo, bo + l*DD, x, x, MM, DD, DD, 1|2);
        // h = LN2(x)
        ln_kernel<<<MM, 256>>>(x, ln2s + l*DD, ln2b + l*DD, h);
        // ffn = relu(h @ W1 + b1)
        run_gemm(h, w1, b1 + l*DFF, nullptr, ffn, MM, DFF, DD, 1|4);
        // x = x + ffn @ W2 + b2
        run_gemm(ffn, w2, b2 + l*DD, x, x, MM, DD, DFF, 1|2);
    }

    // h = LNf(x); out = h @ Wout + bout
    ln_kernel<<<MM, 256>>>(x, lnfs, lnfb, h);
    run_gemm(h, Wout, bout, nullptr, out, MM, VV, DD, 1);
}

// round 3
// speedup vs baseline: 2.3411x; 2.3411x over previous
#include <cuda_runtime.h>
#include <cuda_bf16.h>
#include <math.h>
#include <stdint.h>

// Problem constants
#define BB   2
#define TT   2048
#define DD   1024
#define LL   4
#define HH   16
#define HD   64
#define VV   32000
#define DFF  4096
#define MM   (BB*TT)        // 4096 rows
#define QKVD 3072

// ---------------------------------------------------------------------------
// Scratch (device globals; allocation is forbidden)
// ---------------------------------------------------------------------------
__device__ float g_x  [MM*DD];
__device__ float g_h  [MM*DD];
__device__ float g_qkv[MM*QKVD];
__device__ float g_att[MM*DD];
__device__ float g_ffn[MM*DFF];

// bf16 split activations (A side, row-major = K-major)
__device__ __nv_bfloat16 g_ah[MM*DFF];
__device__ __nv_bfloat16 g_al[MM*DFF];

// bf16 split transposed weights (B side, [N,K] K-major)
__device__ __nv_bfloat16 g_wqkvh[LL*QKVD*DD], g_wqkvl[LL*QKVD*DD];
__device__ __nv_bfloat16 g_woh  [LL*DD*DD],   g_wol  [LL*DD*DD];
__device__ __nv_bfloat16 g_w1h  [LL*DFF*DD],  g_w1l  [LL*DFF*DD];
__device__ __nv_bfloat16 g_w2h  [LL*DD*DFF],  g_w2l  [LL*DD*DFF];
__device__ __nv_bfloat16 g_wouth[VV*DD],      g_woutl[VV*DD];

// ---------------------------------------------------------------------------
// PTX helpers (all sm_80-compatible; no 'a'-suffix features)
// ---------------------------------------------------------------------------
__device__ __forceinline__ uint32_t smem_u32(const void* p) {
    return (uint32_t)__cvta_generic_to_shared(p);
}
#define CP_ASYNC16(dst, src) \
    asm volatile("cp.async.cg.shared.global [%0], [%1], 16;" :: "r"(dst), "l"(src))
#define CP_COMMIT() asm volatile("cp.async.commit_group;" ::: "memory")
#define CP_WAIT0()  asm volatile("cp.async.wait_group 0;" ::: "memory")
#define CP_WAIT1()  asm volatile("cp.async.wait_group 1;" ::: "memory")

__device__ __forceinline__ void ldmat_x4(uint32_t* r, uint32_t addr) {
    asm volatile("ldmatrix.sync.aligned.m8n8.x4.shared.b16 {%0,%1,%2,%3}, [%4];"
                 : "=r"(r[0]), "=r"(r[1]), "=r"(r[2]), "=r"(r[3]) : "r"(addr));
}
__device__ __forceinline__ void mma16816(float* d, const uint32_t* a,
                                         const uint32_t* b) {
    asm volatile(
        "mma.sync.aligned.m16n8k16.row.col.f32.bf16.bf16.f32 "
        "{%0,%1,%2,%3}, {%4,%5,%6,%7}, {%8,%9}, {%0,%1,%2,%3};"
        : "+f"(d[0]), "+f"(d[1]), "+f"(d[2]), "+f"(d[3])
        : "r"(a[0]), "r"(a[1]), "r"(a[2]), "r"(a[3]), "r"(b[0]), "r"(b[1]));
}

// ---------------------------------------------------------------------------
// tcgen-free tensor GEMM: C[M,N] = (Ah+Al)[M,K] @ (Bh+Bl)[N,K]^T  (3xBF16)
// CTA tile 128x256, BK=32, 256 threads (2x4 warps, 64x64 warp tile),
// cp.async double-buffered smem, fp32 accumulators.
// mode: bit0 = +bias[n], bit1 = +res[m,n], bit2 = relu
// ---------------------------------------------------------------------------
#define TM 128
#define TN 256
#define BK 32
#define SA 40                       // padded row stride in elements (80 B)
#define A_ELE (TM*SA)
#define B_ELE (TN*SA)
#define A_BYT (A_ELE*2)             // 10240
#define B_BYT (B_ELE*2)             // 20480
#define STAGE_ELE (2*A_ELE + 2*B_ELE)
#define STAGE_BYT (STAGE_ELE*2)     // 61440
#define GEMM_SMEM (2*STAGE_BYT)     // 122880

// load a [rows x 32] bf16 tile (row-major, ld=K) into padded smem
__device__ __forceinline__ void load_tile(uint32_t sdst, const __nv_bfloat16* g,
                                          int K, int k0, int rows4, int tid) {
    for (int i = tid; i < rows4; i += 256) {
        int r = i >> 2, gg = i & 3;
        CP_ASYNC16(sdst + (uint32_t)(r * 80 + gg * 16),
                   (const void*)(g + (size_t)r * K + k0 + gg * 8));
    }
}

__global__ void __launch_bounds__(256) tc_gemm(
    int M, int N, int K,
    const __nv_bfloat16* __restrict__ Ah, const __nv_bfloat16* __restrict__ Al,
    const __nv_bfloat16* __restrict__ Bh, const __nv_bfloat16* __restrict__ Bl,
    const float* __restrict__ bias, const float* __restrict__ res,
    float* __restrict__ C, int mode)
{
    extern __shared__ __nv_bfloat16 sm[];
    uint32_t sbase = smem_u32(sm);
    int tid = threadIdx.x;
    int bm = blockIdx.y, bn = blockIdx.x;
    int warp = tid >> 5, lane = tid & 31;
    int wm = warp & 1, wn = warp >> 1;          // warp grid 2 x 4

    const __nv_bfloat16* gAh = Ah + (size_t)bm * TM * K;
    const __nv_bfloat16* gAl = Al + (size_t)bm * TM * K;
    const __nv_bfloat16* gBh = Bh + (size_t)bn * TN * K;
    const __nv_bfloat16* gBl = Bl + (size_t)bn * TN * K;

    float acc[4][8][4];
    #pragma unroll
    for (int i = 0; i < 4; i++)
        #pragma unroll
        for (int j = 0; j < 8; j++)
            #pragma unroll
            for (int u = 0; u < 4; u++) acc[i][j][u] = 0.f;

    // ldmatrix lane geometry (shared by A and B): lane L reads row of mat L>>3
    int mat = lane >> 3;
    int row_off = (mat & 1) * 8 + (lane & 7);   // +0/+8 within 16-row group
    int kblk_off = (mat >> 1) * 8;              // +0/+8 within k16

    const int NC = K / BK;

    // prologue: chunk 0 -> stage 0
    load_tile(sbase,                     gAh, K, 0, TM*4, tid);
    load_tile(sbase + A_BYT,             gAl, K, 0, TM*4, tid);
    load_tile(sbase + 2*A_BYT,           gBh, K, 0, TN*4, tid);
    load_tile(sbase + 2*A_BYT + B_BYT,   gBl, K, 0, TN*4, tid);
    CP_COMMIT();

    for (int c = 0; c < NC; c++) {
        int s = c & 1;
        if (c + 1 < NC) {
            uint32_t nb = sbase + (uint32_t)((s ^ 1) * STAGE_BYT);
            int k0 = (c + 1) * BK;
            load_tile(nb,                   gAh, K, k0, TM*4, tid);
            load_tile(nb + A_BYT,           gAl, K, k0, TM*4, tid);
            load_tile(nb + 2*A_BYT,         gBh, K, k0, TN*4, tid);
            load_tile(nb + 2*A_BYT + B_BYT, gBl, K, k0, TN*4, tid);
            CP_COMMIT();
            CP_WAIT1();
        } else {
            CP_WAIT0();
        }
        __syncthreads();

        uint32_t stg = sbase + (uint32_t)(s * STAGE_BYT);
        #pragma unroll
        for (int pass = 0; pass < 3; pass++) {
            uint32_t As = (pass == 2) ? (stg + A_BYT) : stg;
            uint32_t Bs = (pass == 1) ? (stg + 2*A_BYT + B_BYT) : (stg + 2*A_BYT);
            #pragma unroll
            for (int ks = 0; ks < 2; ks++) {
                int k0 = ks * 16;
                uint32_t af[4][4], bf[4][4];
                #pragma unroll
                for (int mt = 0; mt < 4; mt++) {
                    int r = wm * 64 + mt * 16 + row_off;
                    ldmat_x4(af[mt], As + (uint32_t)((r * SA + k0 + kblk_off) * 2));
                }
                #pragma unroll
                for (int ng = 0; ng < 4; ng++) {
                    int r = wn * 64 + ng * 16 + row_off;
                    ldmat_x4(bf[ng], Bs + (uint32_t)((r * SA + k0 + kblk_off) * 2));
                }
                #pragma unroll
                for (int mt = 0; mt < 4; mt++)
                    #pragma unroll
                    for (int nt = 0; nt < 8; nt++) {
                        uint32_t bb[2] = { bf[nt >> 1][nt & 1],
                                           bf[nt >> 1][2 + (nt & 1)] };
                        mma16816(acc[mt][nt], af[mt], bb);
                    }
            }
        }
        __syncthreads();
    }

    // epilogue: registers -> global, fused bias/residual/relu
    int qr = lane >> 2, qc = (lane & 3) * 2;
    #pragma unroll
    for (int mt = 0; mt < 4; mt++) {
        #pragma unroll
        for (int half = 0; half < 2; half++) {
            int grow = bm * TM + wm * 64 + mt * 16 + half * 8 + qr;
            size_t rowo = (size_t)grow * N;
            #pragma unroll
            for (int nt = 0; nt < 8; nt++) {
                int gcol = bn * TN + wn * 64 + nt * 8 + qc;
                float v0 = acc[mt][nt][half * 2 + 0];
                float v1 = acc[mt][nt][half * 2 + 1];
                if (mode & 1) { v0 += bias[gcol]; v1 += bias[gcol + 1]; }
                if (mode & 2) {
                    const float2 r2 = *(const float2*)(res + rowo + gcol);
                    v0 += r2.x; v1 += r2.y;
                }
                if (mode & 4) { v0 = fmaxf(v0, 0.f); v1 = fmaxf(v1, 0.f); }
                float2 o2; o2.x = v0; o2.y = v1;
                *(float2*)(C + rowo + gcol) = o2;
            }
        }
    }
}

// ---------------------------------------------------------------------------
// Elementwise split: fp32 -> (hi, lo) bf16
// ---------------------------------------------------------------------------
__global__ __launch_bounds__(256) void split_kernel(
    const float* __restrict__ A, __nv_bfloat16* __restrict__ Ah,
    __nv_bfloat16* __restrict__ Al, int n)
{
    int i = blockIdx.x * 256 + threadIdx.x;
    if (i < n) {
        float v = A[i];
        __nv_bfloat16 hi = __float2bfloat16(v);
        Ah[i] = hi;
        Al[i] = __float2bfloat16(v - __bfloat162float(hi));
    }
}

// ---------------------------------------------------------------------------
// Weight transpose + split: W[K,N] fp32 -> Bt{h,l}[N,K] bf16
// ---------------------------------------------------------------------------
__global__ __launch_bounds__(256) void transpose_split_kernel(
    const float* __restrict__ W, __nv_bfloat16* __restrict__ Bh,
    __nv_bfloat16* __restrict__ Bl, int K, int N)
{
    __shared__ float t[32][33];
    int n0 = blockIdx.x * 32, k0 = blockIdx.y * 32;
    int tx = threadIdx.x & 31, ty = threadIdx.x >> 5;   // ty 0..7
    #pragma unroll
    for (int i = 0; i < 32; i += 8)
        t[ty + i][tx] = W[(size_t)(k0 + ty + i) * N + n0 + tx];
    __syncthreads();
    #pragma unroll
    for (int i = 0; i < 32; i += 8) {
        float v = t[tx][ty + i];               // = W[k0+tx][n0+ty+i]
        __nv_bfloat16 hi = __float2bfloat16(v);
        size_t o = (size_t)(n0 + ty + i) * K + k0 + tx;
        Bh[o] = hi;
        Bl[o] = __float2bfloat16(v - __bfloat162float(hi));
    }
}

// ---------------------------------------------------------------------------
// Embedding
// ---------------------------------------------------------------------------
__global__ __launch_bounds__(256) void embed_kernel(
    const int* __restrict__ ctx, const float* __restrict__ tok,
    const float* __restrict__ pos, float* __restrict__ x)
{
    int idx = blockIdx.x * 256 + threadIdx.x;
    int d  = idx & (DD - 1);
    int bt = idx >> 10;
    int t  = bt & (TT - 1);
    int v  = ctx[bt];
    x[idx] = tok[(size_t)v * DD + d] + pos[(size_t)t * DD + d];
}

// ---------------------------------------------------------------------------
// LayerNorm
// ---------------------------------------------------------------------------
__global__ __launch_bounds__(256) void ln_kernel(
    const float* __restrict__ x, const float* __restrict__ s,
    const float* __restrict__ b, float* __restrict__ y)
{
    int row = blockIdx.x;
    const float* xr = x + (size_t)row * DD;
    float*       yr = y + (size_t)row * DD;
    int tid = threadIdx.x;

    float v0 = xr[tid], v1 = xr[tid+256], v2 = xr[tid+512], v3 = xr[tid+768];
    float sum = v0+v1+v2+v3;
    float sq  = v0*v0+v1*v1+v2*v2+v3*v3;
    #pragma unroll
    for (int o = 16; o > 0; o >>= 1) {
        sum += __shfl_xor_sync(0xFFFFFFFFu, sum, o);
        sq  += __shfl_xor_sync(0xFFFFFFFFu, sq,  o);
    }
    __shared__ float ssum[8], ssq[8], red[2];
    if ((tid & 31) == 0) { ssum[tid>>5] = sum; ssq[tid>>5] = sq; }
    __syncthreads();
    if (tid < 32) {
        float a = (tid < 8) ? ssum[tid] : 0.f;
        float c = (tid < 8) ? ssq[tid]  : 0.f;
        #pragma unroll
        for (int o = 4; o > 0; o >>= 1) {
            a += __shfl_xor_sync(0xFFFFFFFFu, a, o);
            c += __shfl_xor_sync(0xFFFFFFFFu, c, o);
        }
        if (tid == 0) { red[0] = a; red[1] = c; }
    }
    __syncthreads();
    float mean = red[0] * (1.f/DD);
    float var  = red[1] * (1.f/DD) - mean*mean;
    float inv  = rsqrtf(var + 1e-5f);
    #pragma unroll
    for (int i = 0; i < 4; i++) {
        int c = tid + i*256;
        yr[c] = (xr[c] - mean) * inv * s[c] + b[c];
    }
}

// ---------------------------------------------------------------------------
// Flash attention (causal), QKV packed [M, 3072], O -> att [M, 1024]
// ---------------------------------------------------------------------------
__global__ __launch_bounds__(128) void attn_kernel(
    const float* __restrict__ QKV, float* __restrict__ O)
{
    int qt = blockIdx.x, h = blockIdx.y, b = blockIdx.z;
    int tid = threadIdx.x;
    int q_idx = qt * 128 + tid;

    const float* qp = QKV + ((size_t)(b*TT) + q_idx) * QKVD + h * HD;

    float qr[64];
    #pragma unroll
    for (int c = 0; c < 16; c++) {
        float4 t4 = *(const float4*)(qp + c*4);
        qr[4*c+0] = t4.x * 0.125f; qr[4*c+1] = t4.y * 0.125f;
        qr[4*c+2] = t4.z * 0.125f; qr[4*c+3] = t4.w * 0.125f;
    }
    float ob[64];
    #pragma unroll
    for (int d = 0; d < 64; d++) ob[d] = 0.f;
    float m = -1e30f, lsum = 0.f;

    __shared__ float4 Ks[16][16];
    __shared__ float4 Vs[16][16];

    int kend = qt * 128 + 128;
    for (int k0 = 0; k0 < kend; k0 += 16) {
        __syncthreads();
        #pragma unroll
        for (int i = 0; i < 2; i++) {
            int idx = tid + i*128;
            int r = idx >> 4, c = idx & 15;
            size_t rb = ((size_t)(b*TT) + k0 + r) * QKVD + h * HD + c*4;
            Ks[r][c] = *(const float4*)(QKV + rb + DD);
            Vs[r][c] = *(const float4*)(QKV + rb + 2*DD);
        }
        __syncthreads();

        float s[16];
        #pragma unroll
        for (int j = 0; j < 16; j++) {
            float acc = 0.f;
            #pragma unroll
            for (int c = 0; c < 16; c++) {
                float4 kk = Ks[j][c];
                acc += qr[4*c+0]*kk.x + qr[4*c+1]*kk.y
                     + qr[4*c+2]*kk.z + qr[4*c+3]*kk.w;
            }
            s[j] = (k0 + j <= q_idx) ? acc : -1e30f;
        }
        float mt = m;
        #pragma unroll
        for (int j = 0; j < 16; j++) mt = fmaxf(mt, s[j]);
        float corr = __expf(m - mt);
        m = mt;
        lsum *= corr;
        #pragma unroll
        for (int d = 0; d < 64; d++) ob[d] *= corr;

        #pragma unroll
        for (int j = 0; j < 16; j++) {
            float p = __expf(s[j] - m);
            lsum += p;
            #pragma unroll
            for (int c = 0; c < 16; c++) {
                float4 vv = Vs[j][c];
                ob[4*c+0] += p * vv.x; ob[4*c+1] += p * vv.y;
                ob[4*c+2] += p * vv.z; ob[4*c+3] += p * vv.w;
            }
        }
    }

    float inv = 1.f / lsum;
    float* op = O + ((size_t)(b*TT) + q_idx) * DD + h * HD;
    #pragma unroll
    for (int c = 0; c < 16; c++) {
        float4 t4;
        t4.x = ob[4*c+0]*inv; t4.y = ob[4*c+1]*inv;
        t4.z = ob[4*c+2]*inv; t4.w = ob[4*c+3]*inv;
        *(float4*)(op + c*4) = t4;
    }
}

// ---------------------------------------------------------------------------
// Host orchestration
// ---------------------------------------------------------------------------
static void launch_gemm(const __nv_bfloat16* Ah, const __nv_bfloat16* Al,
                        const __nv_bfloat16* Bh, const __nv_bfloat16* Bl,
                        const float* bias, const float* res, float* C,
                        int M, int N, int K, int mode)
{
    dim3 grid(N / TN, M / TM);
    tc_gemm<<<grid, 256, GEMM_SMEM>>>(M, N, K, Ah, Al, Bh, Bl, bias, res, C, mode);
}

static void launch_tsplit(const float* W, __nv_bfloat16* Bh, __nv_bfloat16* Bl,
                          int K, int N)
{
    dim3 grid(N / 32, K / 32);
    transpose_split_kernel<<<grid, 256>>>(W, Bh, Bl, K, N);
}

static void launch_split(const float* A, __nv_bfloat16* Ah, __nv_bfloat16* Al, int n)
{
    split_kernel<<<(n + 255) / 256, 256>>>(A, Ah, Al, n);
}

extern "C" void kernel_launch(void* const* d_in, const int* in_sizes, int n_in,
                              void* d_out, int out_size)
{
    const int*   ctx  = (const int*)  d_in[0];
    const float* tok  = (const float*)d_in[1];
    const float* pos  = (const float*)d_in[2];
    const float* Wq   = (const float*)d_in[3];
    const float* Wk   = (const float*)d_in[4];
    const float* Wv   = (const float*)d_in[5];
    const float* Wo   = (const float*)d_in[6];
    const float* bo   = (const float*)d_in[7];
    const float* ln1s = (const float*)d_in[8];
    const float* ln1b = (const float*)d_in[9];
    const float* W1   = (const float*)d_in[10];
    const float* b1   = (const float*)d_in[11];
    const float* W2   = (const float*)d_in[12];
    const float* b2   = (const float*)d_in[13];
    const float* ln2s = (const float*)d_in[14];
    const float* ln2b = (const float*)d_in[15];
    const float* lnfs = (const float*)d_in[16];
    const float* lnfb = (const float*)d_in[17];
    const float* Wout = (const float*)d_in[18];
    const float* bout = (const float*)d_in[19];
    float* out = (float*)d_out;

    cudaFuncSetAttribute(tc_gemm, cudaFuncAttributeMaxDynamicSharedMemorySize, GEMM_SMEM);

    float *x, *h, *qkv, *att, *ffn;
    __nv_bfloat16 *ah, *al, *wqkvh, *wqkvl, *woh, *wol, *w1h, *w1l, *w2h, *w2l, *wouth, *woutl;
    cudaGetSymbolAddress((void**)&x,    g_x);
    cudaGetSymbolAddress((void**)&h,    g_h);
    cudaGetSymbolAddress((void**)&qkv,  g_qkv);
    cudaGetSymbolAddress((void**)&att,  g_att);
    cudaGetSymbolAddress((void**)&ffn,  g_ffn);
    cudaGetSymbolAddress((void**)&ah,   g_ah);
    cudaGetSymbolAddress((void**)&al,   g_al);
    cudaGetSymbolAddress((void**)&wqkvh,g_wqkvh);
    cudaGetSymbolAddress((void**)&wqkvl,g_wqkvl);
    cudaGetSymbolAddress((void**)&woh,  g_woh);
    cudaGetSymbolAddress((void**)&wol,  g_wol);
    cudaGetSymbolAddress((void**)&w1h,  g_w1h);
    cudaGetSymbolAddress((void**)&w1l,  g_w1l);
    cudaGetSymbolAddress((void**)&w2h,  g_w2h);
    cudaGetSymbolAddress((void**)&w2l,  g_w2l);
    cudaGetSymbolAddress((void**)&wouth,g_wouth);
    cudaGetSymbolAddress((void**)&woutl,g_woutl);

    // Weight prep: transpose+split all weights to [N,K] bf16 hi/lo
    for (int l = 0; l < LL; l++) {
        size_t qo = (size_t)l * QKVD * DD;
        launch_tsplit(Wq + (size_t)l*DD*DD, wqkvh + qo,                   wqkvl + qo,                   DD, DD);
        launch_tsplit(Wk + (size_t)l*DD*DD, wqkvh + qo + (size_t)DD*DD,   wqkvl + qo + (size_t)DD*DD,   DD, DD);
        launch_tsplit(Wv + (size_t)l*DD*DD, wqkvh + qo + (size_t)2*DD*DD, wqkvl + qo + (size_t)2*DD*DD, DD, DD);
        launch_tsplit(Wo + (size_t)l*DD*DD,  woh + (size_t)l*DD*DD,  wol + (size_t)l*DD*DD,  DD, DD);
        launch_tsplit(W1 + (size_t)l*DD*DFF, w1h + (size_t)l*DFF*DD, w1l + (size_t)l*DFF*DD, DD, DFF);
        launch_tsplit(W2 + (size_t)l*DFF*DD, w2h + (size_t)l*DD*DFF, w2l + (size_t)l*DD*DFF, DFF, DD);
    }
    launch_tsplit(Wout, wouth, woutl, DD, VV);

    // Embedding
    embed_kernel<<<(MM*DD)/256, 256>>>(ctx, tok, pos, x);

    for (int l = 0; l < LL; l++) {
        const __nv_bfloat16* lwqh = wqkvh + (size_t)l*QKVD*DD;
        const __nv_bfloat16* lwql = wqkvl + (size_t)l*QKVD*DD;
        const __nv_bfloat16* lwoh = woh + (size_t)l*DD*DD;
        const __nv_bfloat16* lwol = wol + (size_t)l*DD*DD;
        const __nv_bfloat16* lw1h = w1h + (size_t)l*DFF*DD;
        const __nv_bfloat16* lw1l = w1l + (size_t)l*DFF*DD;
        const __nv_bfloat16* lw2h = w2h + (size_t)l*DD*DFF;
        const __nv_bfloat16* lw2l = w2l + (size_t)l*DD*DFF;

        // h = LN1(x); split; qkv = h @ [Wq|Wk|Wv]
        ln_kernel<<<MM, 256>>>(x, ln1s + l*DD, ln1b + l*DD, h);
        launch_split(h, ah, al, MM*DD);
        launch_gemm(ah, al, lwqh, lwql, nullptr, nullptr, qkv, MM, QKVD, DD, 0);

        // attention
        {
            dim3 grid(TT/128, HH, BB);
            attn_kernel<<<grid, 128>>>(qkv, att);
        }

        // x = x + att @ Wo + bo
        launch_split(att, ah, al, MM*DD);
        launch_gemm(ah, al, lwoh, lwol, bo + l*DD, x, x, MM, DD, DD, 1|2);

        // h = LN2(x); ffn = relu(h @ W1 + b1)
        ln_kernel<<<MM, 256>>>(x, ln2s + l*DD, ln2b + l*DD, h);
        launch_split(h, ah, al, MM*DD);
        launch_gemm(ah, al, lw1h, lw1l, b1 + l*DFF, nullptr, ffn, MM, DFF, DD, 1|4);

        // x = x + ffn @ W2 + b2
        launch_split(ffn, ah, al, MM*DFF);
        launch_gemm(ah, al, lw2h, lw2l, b2 + l*DD, x, x, MM, DD, DFF, 1|2);
    }

    // final LN + logits
    ln_kernel<<<MM, 256>>>(x, lnfs, lnfb, h);
    launch_split(h, ah, al, MM*DD);
    launch_gemm(ah, al, wouth, woutl, bout, nullptr, out, MM, VV, DD, 1);
}